// round 4
// baseline (speedup 1.0000x reference)
#include <cuda_runtime.h>
#include <math.h>

// Problem constants
#define TSTEPS 128
#define BATCH  1024
#define INDIM  47
#define HID    646
#define OUTDIM 5

// GEMM tiling: 64x64 tile, 128 threads, 8(m)x4(n) microtile, m-paired f32x2
#define MTILE 64
#define NTILE 64
#define KTILE 16
#define TPB   128
#define GRID  444              // 3 CTAs/SM, work-stealing

#define MT (BATCH / MTILE)                 // 16
#define NT ((HID + NTILE - 1) / NTILE)     // 11
#define TILES (MT * NT)                    // 176
#define SZ (BATCH * HID)                   // 661504

typedef unsigned long long ull;

// Double-buffered recurrent state + per-launch work counters (no allocation allowed)
__device__ float g_h0[2][SZ];
__device__ float g_h1[2][SZ];
__device__ unsigned int g_counter[TSTEPS + 2];

struct Job {
    const float* A1; int K1;   // first input segment  (x or h0)
    const float* A2; int K2;   // second input segment (recurrent h)
    const float* W1;           // [HID, K1] row-major
    const float* W2;           // [HID, K2] row-major
    const float* b1;
    const float* b2;
    float* C;                  // [BATCH, HID] output
};

__global__ void init_kernel() {
    int i = blockIdx.x * blockDim.x + threadIdx.x;
    if (i < SZ) {
        g_h0[1][i] = 0.0f;
        g_h1[1][i] = 0.0f;
    }
    if (i < TSTEPS + 2) g_counter[i] = 0u;
}

// ---- packed fp32x2 helpers (Blackwell FFMA2 path; full fp32 precision) ----
__device__ __forceinline__ ull pack2(float x) {
    ull r; asm("mov.b64 %0, {%1, %1};" : "=l"(r) : "f"(x)); return r;
}
__device__ __forceinline__ void fma2(ull& acc, ull a, ull b) {
    asm("fma.rn.f32x2 %0, %1, %2, %0;" : "+l"(acc) : "l"(a), "l"(b));
}
__device__ __forceinline__ float2 unpack2(ull v) {
    float lo, hi; asm("mov.b64 {%0, %1}, %2;" : "=f"(lo), "=f"(hi) : "l"(v));
    return make_float2(lo, hi);
}

// Accumulate C_tile += A[m0:m0+64, :K] * W[n0:n0+64, :K]^T  (both K-contiguous).
// Smem tiles [2][KTILE][68] (stride 68 = 16B-aligned vector reads, conflict-light
// transpose stores). Double-buffered: ONE __syncthreads per k-tile.
// acc[p][j]: f32x2 over rows (mgo+2p, mgo+2p+1), column ngo+j.
__device__ __forceinline__ void gemm_accum(
    const float* __restrict__ A, const float* __restrict__ W, int K,
    int m0, int n0, ull acc[4][4],
    float (*__restrict__ As)[KTILE * 68], float (*__restrict__ Bs)[KTILE * 68],
    int tid)
{
    const int lrow = tid >> 1;          // 0..63 : tile row (m for A, n for W)
    const int lk8  = (tid & 1) << 3;    // 0 or 8 : k offset group
    const int mgo  = (tid & 7) << 3;    // micro-tile m offset (8 rows)
    const int ngo  = (tid >> 3) << 2;   // micro-tile n offset (4 cols)

    const float* Arow = A + (size_t)(m0 + lrow) * K;
    const bool wv = (n0 + lrow) < HID;
    const float* Wrow = W + (size_t)(wv ? (n0 + lrow) : 0) * K;

    const int nk = (K + KTILE - 1) / KTILE;

    float ra[8], rb[8];
    #pragma unroll
    for (int i = 0; i < 8; i++) {
        int k = lk8 + i;
        ra[i] = (k < K) ? Arow[k] : 0.0f;
        rb[i] = (k < K && wv) ? Wrow[k] : 0.0f;
    }
    #pragma unroll
    for (int i = 0; i < 8; i++) {
        As[0][(lk8 + i) * 68 + lrow] = ra[i];
        Bs[0][(lk8 + i) * 68 + lrow] = rb[i];
    }
    __syncthreads();

    for (int kt = 0; kt < nk; kt++) {
        const int kn = (kt + 1) * KTILE;
        if (kt + 1 < nk) {
            #pragma unroll
            for (int i = 0; i < 8; i++) {
                int k = kn + lk8 + i;
                ra[i] = (k < K) ? Arow[k] : 0.0f;
                rb[i] = (k < K && wv) ? Wrow[k] : 0.0f;
            }
        }

        const float* as = As[kt & 1];
        const float* bs = Bs[kt & 1];
        #pragma unroll
        for (int kk = 0; kk < KTILE; kk++) {
            const float* ap = as + kk * 68 + mgo;
            ulonglong2 a01 = *(const ulonglong2*)(ap);      // m-pairs (0,1),(2,3)
            ulonglong2 a23 = *(const ulonglong2*)(ap + 4);  // m-pairs (4,5),(6,7)
            float4 bv = *(const float4*)(bs + kk * 68 + ngo);
            ull b0 = pack2(bv.x), b1 = pack2(bv.y), b2 = pack2(bv.z), b3 = pack2(bv.w);
            fma2(acc[0][0], a01.x, b0); fma2(acc[0][1], a01.x, b1);
            fma2(acc[0][2], a01.x, b2); fma2(acc[0][3], a01.x, b3);
            fma2(acc[1][0], a01.y, b0); fma2(acc[1][1], a01.y, b1);
            fma2(acc[1][2], a01.y, b2); fma2(acc[1][3], a01.y, b3);
            fma2(acc[2][0], a23.x, b0); fma2(acc[2][1], a23.x, b1);
            fma2(acc[2][2], a23.x, b2); fma2(acc[2][3], a23.x, b3);
            fma2(acc[3][0], a23.y, b0); fma2(acc[3][1], a23.y, b1);
            fma2(acc[3][2], a23.y, b2); fma2(acc[3][3], a23.y, b3);
        }

        if (kt + 1 < nk) {
            const int nb = (kt + 1) & 1;
            #pragma unroll
            for (int i = 0; i < 8; i++) {
                As[nb][(lk8 + i) * 68 + lrow] = ra[i];
                Bs[nb][(lk8 + i) * 68 + lrow] = rb[i];
            }
        }
        __syncthreads();
    }
}

// Work-stealing cell kernel. Tile indices [0, TILES) -> jH (heavy, dispatched
// first); [TILES, ntiles) -> jL. Each tile: C = tanh(A1@W1^T + b1 + A2@W2^T + b2).
__global__ __launch_bounds__(TPB) void cell_kernel(Job jH, Job jL,
                                                   int cidx, int ntiles) {
    __shared__ float As[2][KTILE * 68];
    __shared__ float Bs[2][KTILE * 68];
    __shared__ unsigned int s_idx;

    const int tid = threadIdx.x;

    for (;;) {
        if (tid == 0) s_idx = atomicAdd(&g_counter[cidx], 1u);
        __syncthreads();
        const unsigned int idx = s_idx;
        if (idx >= (unsigned int)ntiles) break;

        const Job jb = (idx < TILES) ? jH : jL;
        const int tile = (idx < TILES) ? (int)idx : (int)idx - TILES;
        const int m0 = (tile / NT) * MTILE;
        const int n0 = (tile % NT) * NTILE;

        ull acc[4][4] = {};   // zero bits == {0.f, 0.f}
        gemm_accum(jb.A1, jb.W1, jb.K1, m0, n0, acc, As, Bs, tid);
        gemm_accum(jb.A2, jb.W2, jb.K2, m0, n0, acc, As, Bs, tid);

        const int mgo = (tid & 7) << 3;
        const int ngo = (tid >> 3) << 2;
        const int mrow = m0 + mgo;
        #pragma unroll
        for (int j = 0; j < 4; j++) {
            const int n = n0 + ngo + j;
            if (n < HID) {
                const float bias = jb.b1[n] + jb.b2[n];
                #pragma unroll
                for (int p = 0; p < 4; p++) {
                    float2 v = unpack2(acc[p][j]);
                    jb.C[(size_t)(mrow + 2 * p) * HID + n]     = tanhf(v.x + bias);
                    jb.C[(size_t)(mrow + 2 * p + 1) * HID + n] = tanhf(v.y + bias);
                }
            }
        }
        // gemm_accum ends with __syncthreads(); epilogue touches no smem,
        // and the loop-top sync guards the s_idx handoff.
    }
}

// logits[b,o] = h1[b,:] . Wout[o,:] + bout[o] ; one warp per (b,o)
__global__ void classifier_kernel(const float* __restrict__ h,
                                  const float* __restrict__ Wout,
                                  const float* __restrict__ bout,
                                  float* __restrict__ out) {
    int warp = (blockIdx.x * blockDim.x + threadIdx.x) >> 5;
    int lane = threadIdx.x & 31;
    if (warp >= BATCH * OUTDIM) return;
    int b = warp / OUTDIM, o = warp % OUTDIM;
    const float* hr = h + (size_t)b * HID;
    const float* wr = Wout + (size_t)o * HID;
    float s = 0.0f;
    for (int k = lane; k < HID; k += 32) s += hr[k] * wr[k];
    #pragma unroll
    for (int off = 16; off; off >>= 1) s += __shfl_down_sync(0xffffffff, s, off);
    if (lane == 0) out[b * OUTDIM + o] = s + bout[o];
}

extern "C" void kernel_launch(void* const* d_in, const int* in_sizes, int n_in,
                              void* d_out, int out_size) {
    const float* xs   = (const float*)d_in[0];
    const float* Wih0 = (const float*)d_in[1];
    const float* Whh0 = (const float*)d_in[2];
    const float* bih0 = (const float*)d_in[3];
    const float* bhh0 = (const float*)d_in[4];
    const float* Wih1 = (const float*)d_in[5];
    const float* Whh1 = (const float*)d_in[6];
    const float* bih1 = (const float*)d_in[7];
    const float* bhh1 = (const float*)d_in[8];
    const float* Wout = (const float*)d_in[9];
    const float* bout = (const float*)d_in[10];
    float* out = (float*)d_out;

    void* p;
    cudaGetSymbolAddress(&p, g_h0);
    float* h0b = (float*)p;              // h0b + parity*SZ
    cudaGetSymbolAddress(&p, g_h1);
    float* h1b = (float*)p;

    // zero the "t = -1" state slots (parity 1) and all work counters
    init_kernel<<<(SZ + 255) / 256, 256>>>();

    // t = 0: layer0 only  h0(0) = f(x0, h0(-1)=0)
    {
        Job j0 = { xs, INDIM, h0b + SZ, HID, Wih0, Whh0, bih0, bhh0, h0b };
        cell_kernel<<<GRID, TPB>>>(j0, j0, 0, TILES);
    }

    // t = 1..127: fused  h0(t) = f(x_t, h0(t-1))  ||  h1(t-1) = g(h0(t-1), h1(t-2))
    for (int t = 1; t < TSTEPS; t++) {
        const float* h0_prev = h0b + (size_t)((t - 1) & 1) * SZ;
        Job j0 = { xs + (size_t)t * BATCH * INDIM, INDIM,
                   h0_prev, HID,
                   Wih0, Whh0, bih0, bhh0,
                   h0b + (size_t)(t & 1) * SZ };
        Job j1 = { h0_prev, HID,
                   h1b + (size_t)(t & 1) * SZ,      // h1(t-2) lives at parity t%2
                   HID,
                   Wih1, Whh1, bih1, bhh1,
                   h1b + (size_t)((t - 1) & 1) * SZ };
        // heavy job (K=1292) dispatched first, light tail
        cell_kernel<<<GRID, TPB>>>(j1, j0, t, 2 * TILES);
    }

    // drain: h1(127) = g(h0(127), h1(126))
    {
        Job jf = { h0b + SZ /* h0(127), parity 1 */, HID,
                   h1b /* h1(126), parity 0 */, HID,
                   Wih1, Whh1, bih1, bhh1,
                   h1b + SZ /* h1(127), parity 1 */ };
        cell_kernel<<<GRID, TPB>>>(jf, jf, TSTEPS, TILES);
    }

    // classifier on h1(127)
    classifier_kernel<<<(BATCH * OUTDIM * 32 + 255) / 256, 256>>>(h1b + SZ, Wout, bout, out);
}

// round 5
// speedup vs baseline: 1.7204x; 1.7204x over previous
#include <cuda_runtime.h>
#include <math.h>

// Problem constants
#define TSTEPS 128
#define BATCH  1024
#define INDIM  47
#define HID    646
#define OUTDIM 5

// GEMM tiling: 64x64 tile, 256 threads, 4x4 microtile, packed f32x2 FMA
#define MTILE 64
#define NTILE 64
#define KTILE 16
#define TPB   256
#define GRID  296              // 2 CTAs / SM, work-stealing

#define MT (BATCH / MTILE)                 // 16
#define NT ((HID + NTILE - 1) / NTILE)     // 11
#define TILES (MT * NT)                    // 176
#define SZ (BATCH * HID)                   // 661504

typedef unsigned long long ull;

// Double-buffered recurrent state + per-launch work counters (no allocation allowed)
__device__ float g_h0[2][SZ];
__device__ float g_h1[2][SZ];
__device__ unsigned int g_counter[TSTEPS + 2];

struct Job {
    const float* A1; int K1;   // first input segment  (x or h0)
    const float* A2; int K2;   // second input segment (recurrent h)
    const float* W1;           // [HID, K1] row-major
    const float* W2;           // [HID, K2] row-major
    const float* b1;
    const float* b2;
    float* C;                  // [BATCH, HID] output
};

__global__ void init_kernel() {
    int i = blockIdx.x * blockDim.x + threadIdx.x;
    if (i < SZ) {
        g_h0[1][i] = 0.0f;
        g_h1[1][i] = 0.0f;
    }
    if (i < TSTEPS + 2) g_counter[i] = 0u;
}

// ---- packed fp32x2 helpers (Blackwell FFMA2 path; full fp32 precision) ----
__device__ __forceinline__ ull pack2(float x) {
    ull r; asm("mov.b64 %0, {%1, %1};" : "=l"(r) : "f"(x)); return r;
}
__device__ __forceinline__ void fma2(ull& acc, ull a, ull b) {
    asm("fma.rn.f32x2 %0, %1, %2, %0;" : "+l"(acc) : "l"(a), "l"(b));
}
__device__ __forceinline__ float2 unpack2(ull v) {
    float lo, hi; asm("mov.b64 {%0, %1}, %2;" : "=f"(lo), "=f"(hi) : "l"(v));
    return make_float2(lo, hi);
}

// Fast tanh: 1 - 2/(e^{2x}+1).  MUFU.EX2 + MUFU.RCP path, rel err ~1e-6.
// Saturates correctly: x->+inf: e=inf -> 1-0 = 1; x->-inf: e=0 -> 1-2 = -1.
__device__ __forceinline__ float fast_tanh(float x) {
    float e = __expf(2.0f * x);
    return 1.0f - __fdividef(2.0f, e + 1.0f);
}

// Accumulate C_tile += A[m0:m0+64, :K] * W[n0:n0+64, :K]^T  (both K-contiguous).
// Smem tiles are [2][KTILE][68]: stride 68 keeps 16B alignment for the vector
// reads; double-buffered so there is ONE __syncthreads per k-tile.
// Store mapping lrow=tid&63, lk4=(tid>>6)*4 => all 32 lanes of a warp store the
// same k to 32 distinct banks: conflict-free STS.
// acc[i][j] is an f32x2 pair over columns (ngo+2j, ngo+2j+1) for row mgo+i.
__device__ __forceinline__ void gemm_accum(
    const float* __restrict__ A, const float* __restrict__ W, int K,
    int m0, int n0, ull acc[4][2],
    float (*__restrict__ As)[KTILE * 68], float (*__restrict__ Bs)[KTILE * 68],
    int tid)
{
    const int lrow = tid & 63;          // 0..63 : tile row (m for A, n for W)
    const int lk4  = (tid >> 6) << 2;   // 0,4,8,12 : k offset group
    const int mgo  = (tid & 15) << 2;   // micro-tile m offset
    const int ngo  = (tid >> 4) << 2;   // micro-tile n offset

    const float* Arow = A + (size_t)(m0 + lrow) * K;
    const bool wv = (n0 + lrow) < HID;
    const float* Wrow = W + (size_t)(wv ? (n0 + lrow) : 0) * K;

    const int nk = (K + KTILE - 1) / KTILE;

    float ra[4], rb[4];
    #pragma unroll
    for (int i = 0; i < 4; i++) {
        int k = lk4 + i;
        ra[i] = (k < K) ? Arow[k] : 0.0f;
        rb[i] = (k < K && wv) ? Wrow[k] : 0.0f;
    }
    #pragma unroll
    for (int i = 0; i < 4; i++) {
        As[0][(lk4 + i) * 68 + lrow] = ra[i];
        Bs[0][(lk4 + i) * 68 + lrow] = rb[i];
    }
    __syncthreads();

    for (int kt = 0; kt < nk; kt++) {
        const int kn = (kt + 1) * KTILE;
        if (kt + 1 < nk) {
            #pragma unroll
            for (int i = 0; i < 4; i++) {
                int k = kn + lk4 + i;
                ra[i] = (k < K) ? Arow[k] : 0.0f;
                rb[i] = (k < K && wv) ? Wrow[k] : 0.0f;
            }
        }

        const float* as = As[kt & 1];
        const float* bs = Bs[kt & 1];
        #pragma unroll
        for (int kk = 0; kk < KTILE; kk++) {
            float4 a = *(const float4*)(as + kk * 68 + mgo);
            ulonglong2 b = *(const ulonglong2*)(bs + kk * 68 + ngo);
            ull a0 = pack2(a.x), a1 = pack2(a.y), a2 = pack2(a.z), a3 = pack2(a.w);
            fma2(acc[0][0], a0, b.x); fma2(acc[0][1], a0, b.y);
            fma2(acc[1][0], a1, b.x); fma2(acc[1][1], a1, b.y);
            fma2(acc[2][0], a2, b.x); fma2(acc[2][1], a2, b.y);
            fma2(acc[3][0], a3, b.x); fma2(acc[3][1], a3, b.y);
        }

        if (kt + 1 < nk) {
            const int nb = (kt + 1) & 1;
            #pragma unroll
            for (int i = 0; i < 4; i++) {
                As[nb][(lk4 + i) * 68 + lrow] = ra[i];
                Bs[nb][(lk4 + i) * 68 + lrow] = rb[i];
            }
        }
        __syncthreads();
    }
}

// Work-stealing cell kernel. Tile indices [0, TILES) -> jH (heavy, dispatched
// first); [TILES, ntiles) -> jL. Each tile: C = tanh(A1@W1^T + b1 + A2@W2^T + b2).
__global__ __launch_bounds__(TPB) void cell_kernel(Job jH, Job jL,
                                                   int cidx, int ntiles) {
    __shared__ float As[2][KTILE * 68];
    __shared__ float Bs[2][KTILE * 68];
    __shared__ unsigned int s_idx;

    const int tid = threadIdx.x;

    for (;;) {
        if (tid == 0) s_idx = atomicAdd(&g_counter[cidx], 1u);
        __syncthreads();
        const unsigned int idx = s_idx;
        if (idx >= (unsigned int)ntiles) break;

        const Job jb = (idx < TILES) ? jH : jL;
        const int tile = (idx < TILES) ? (int)idx : (int)idx - TILES;
        const int m0 = (tile / NT) * MTILE;
        const int n0 = (tile % NT) * NTILE;

        ull acc[4][2] = {};   // zero bits == {0.f, 0.f}
        gemm_accum(jb.A1, jb.W1, jb.K1, m0, n0, acc, As, Bs, tid);
        gemm_accum(jb.A2, jb.W2, jb.K2, m0, n0, acc, As, Bs, tid);

        const int mgo = (tid & 15) << 2;
        const int ngo = (tid >> 4) << 2;
        #pragma unroll
        for (int j = 0; j < 2; j++) {
            const int c0 = n0 + ngo + 2 * j;
            if (c0 < HID) {   // HID even, c0 even -> pair fully valid
                const float blo = jb.b1[c0] + jb.b2[c0];
                const float bhi = jb.b1[c0 + 1] + jb.b2[c0 + 1];
                #pragma unroll
                for (int i = 0; i < 4; i++) {
                    float2 v = unpack2(acc[i][j]);
                    float2 o = make_float2(fast_tanh(v.x + blo), fast_tanh(v.y + bhi));
                    *(float2*)(jb.C + (size_t)(m0 + mgo + i) * HID + c0) = o;
                }
            }
        }
        // gemm_accum ends with __syncthreads(); epilogue touches no smem,
        // and the loop-top sync guards the s_idx handoff.
    }
}

// logits[b,o] = h1[b,:] . Wout[o,:] + bout[o] ; one warp per (b,o)
__global__ void classifier_kernel(const float* __restrict__ h,
                                  const float* __restrict__ Wout,
                                  const float* __restrict__ bout,
                                  float* __restrict__ out) {
    int warp = (blockIdx.x * blockDim.x + threadIdx.x) >> 5;
    int lane = threadIdx.x & 31;
    if (warp >= BATCH * OUTDIM) return;
    int b = warp / OUTDIM, o = warp % OUTDIM;
    const float* hr = h + (size_t)b * HID;
    const float* wr = Wout + (size_t)o * HID;
    float s = 0.0f;
    for (int k = lane; k < HID; k += 32) s += hr[k] * wr[k];
    #pragma unroll
    for (int off = 16; off; off >>= 1) s += __shfl_down_sync(0xffffffff, s, off);
    if (lane == 0) out[b * OUTDIM + o] = s + bout[o];
}

extern "C" void kernel_launch(void* const* d_in, const int* in_sizes, int n_in,
                              void* d_out, int out_size) {
    const float* xs   = (const float*)d_in[0];
    const float* Wih0 = (const float*)d_in[1];
    const float* Whh0 = (const float*)d_in[2];
    const float* bih0 = (const float*)d_in[3];
    const float* bhh0 = (const float*)d_in[4];
    const float* Wih1 = (const float*)d_in[5];
    const float* Whh1 = (const float*)d_in[6];
    const float* bih1 = (const float*)d_in[7];
    const float* bhh1 = (const float*)d_in[8];
    const float* Wout = (const float*)d_in[9];
    const float* bout = (const float*)d_in[10];
    float* out = (float*)d_out;

    void* p;
    cudaGetSymbolAddress(&p, g_h0);
    float* h0b = (float*)p;              // h0b + parity*SZ
    cudaGetSymbolAddress(&p, g_h1);
    float* h1b = (float*)p;

    // zero the "t = -1" state slots (parity 1) and all work counters
    init_kernel<<<(SZ + 255) / 256, 256>>>();

    // t = 0: layer0 only  h0(0) = f(x0, h0(-1)=0)
    {
        Job j0 = { xs, INDIM, h0b + SZ, HID, Wih0, Whh0, bih0, bhh0, h0b };
        cell_kernel<<<GRID, TPB>>>(j0, j0, 0, TILES);
    }

    // t = 1..127: fused  h0(t) = f(x_t, h0(t-1))  ||  h1(t-1) = g(h0(t-1), h1(t-2))
    for (int t = 1; t < TSTEPS; t++) {
        const float* h0_prev = h0b + (size_t)((t - 1) & 1) * SZ;
        Job j0 = { xs + (size_t)t * BATCH * INDIM, INDIM,
                   h0_prev, HID,
                   Wih0, Whh0, bih0, bhh0,
                   h0b + (size_t)(t & 1) * SZ };
        Job j1 = { h0_prev, HID,
                   h1b + (size_t)(t & 1) * SZ,      // h1(t-2) lives at parity t%2
                   HID,
                   Wih1, Whh1, bih1, bhh1,
                   h1b + (size_t)((t - 1) & 1) * SZ };
        // heavy job (K=1292) dispatched first, light tail
        cell_kernel<<<GRID, TPB>>>(j1, j0, t, 2 * TILES);
    }

    // drain: h1(127) = g(h0(127), h1(126))
    {
        Job jf = { h0b + SZ /* h0(127), parity 1 */, HID,
                   h1b /* h1(126), parity 0 */, HID,
                   Wih1, Whh1, bih1, bhh1,
                   h1b + SZ /* h1(127), parity 1 */ };
        cell_kernel<<<GRID, TPB>>>(jf, jf, TSTEPS, TILES);
    }

    // classifier on h1(127)
    classifier_kernel<<<(BATCH * OUTDIM * 32 + 255) / 256, 256>>>(h1b + SZ, Wout, bout, out);
}

// round 7
// speedup vs baseline: 3.5608x; 2.0697x over previous
#include <cuda_runtime.h>
#include <cuda_bf16.h>
#include <stdint.h>
#include <math.h>

// ---------------- problem constants ----------------
#define TSTEPS 128
#define BATCH  1024
#define INDIM  47
#define HID    646
#define OUTDIM 5

// ---------------- tiling ----------------
#define MTILE 128
#define NTILE 64
#define KC    32                  // k-chunk (bf16)
#define NT    11                  // 704/64
#define MT    8                   // 1024/128
#define TILES 88                  // per job
#define NPAD  704
#define HPAD  704
#define XPAD  64
#define TPB   256
#define GRID  296

#define SST    40                 // smem row stride (bf16)
#define A_TILE (MTILE * SST)      // 5120 bf16
#define W_TILE (NTILE * SST)      // 2560 bf16
#define STAGE  (2 * A_TILE + 2 * W_TILE)   // 15360 bf16
#define SMEM_BYTES (2 * STAGE * 2)         // 61440 B

// ---------------- device globals (no allocation allowed) ----------------
#define W_IH0_OFF 0
#define W_HH0_OFF (NPAD * XPAD)
#define W_IH1_OFF (W_HH0_OFF + NPAD * HPAD)
#define W_HH1_OFF (W_IH1_OFF + NPAD * HPAD)
#define W_TOT     (W_HH1_OFF + NPAD * HPAD)

__device__ __nv_bfloat16 gx_h[(size_t)TSTEPS * BATCH * XPAD];
__device__ __nv_bfloat16 gx_l[(size_t)TSTEPS * BATCH * XPAD];
__device__ __nv_bfloat16 gW_h[W_TOT];
__device__ __nv_bfloat16 gW_l[W_TOT];
__device__ __nv_bfloat16 gh0_h[2 * BATCH * HPAD];
__device__ __nv_bfloat16 gh0_l[2 * BATCH * HPAD];
__device__ __nv_bfloat16 gh1_h[2 * BATCH * HPAD];
__device__ __nv_bfloat16 gh1_l[2 * BATCH * HPAD];
__device__ unsigned int  g_counter[TSTEPS + 2];

// ---------------- helpers ----------------
__device__ __forceinline__ uint32_t pkbf(float lo, float hi) {
    uint32_t r;
    asm("cvt.rn.bf16x2.f32 %0, %1, %2;" : "=r"(r) : "f"(hi), "f"(lo));
    return r;
}
__device__ __forceinline__ float fast_tanh(float x) {
    float e = __expf(2.0f * x);
    return 1.0f - __fdividef(2.0f, e + 1.0f);
}
// D += A(bf16 m16k16 row) * B(bf16 n8k16 col), fp32 accum
__device__ __forceinline__ void mma_bf16(float* d, const uint32_t a[4], const uint32_t b[2]) {
    asm volatile(
        "mma.sync.aligned.m16n8k16.row.col.f32.bf16.bf16.f32 "
        "{%0,%1,%2,%3}, {%4,%5,%6,%7}, {%8,%9}, {%0,%1,%2,%3};"
        : "+f"(d[0]), "+f"(d[1]), "+f"(d[2]), "+f"(d[3])
        : "r"(a[0]), "r"(a[1]), "r"(a[2]), "r"(a[3]), "r"(b[0]), "r"(b[1]));
}

// ---------------- preprocessing ----------------
__global__ void convert_pad_kernel(__nv_bfloat16* dh, __nv_bfloat16* dl,
                                   const float* __restrict__ src,
                                   int rreal, int creal, int cpad, long total) {
    long i = (long)blockIdx.x * blockDim.x + threadIdx.x;
    if (i >= total) return;
    int r = (int)(i / cpad), c = (int)(i % cpad);
    float v = (r < rreal && c < creal) ? src[(long)r * creal + c] : 0.0f;
    __nv_bfloat16 hi = __float2bfloat16(v);
    dh[i] = hi;
    dl[i] = __float2bfloat16(v - __bfloat162float(hi));
}

__global__ void init_kernel() {
    int i = blockIdx.x * blockDim.x + threadIdx.x;
    __nv_bfloat16 z = __float2bfloat16(0.0f);
    if (i < 2 * BATCH * HPAD) {
        gh0_h[i] = z; gh0_l[i] = z; gh1_h[i] = z; gh1_l[i] = z;
    }
    if (i < TSTEPS + 2) g_counter[i] = 0u;
}

// ---------------- cell kernel ----------------
struct Seg {
    const __nv_bfloat16 *Ah, *Al;   // activations [rows][kpad]
    const __nv_bfloat16 *Wh, *Wl;   // weights [NPAD][kpad]
    int kpad, chunks;
};
struct Job {
    Seg s[2];
    const float *b1, *b2;
    __nv_bfloat16 *Ch, *Cl;          // output [BATCH][HPAD] hi/lo
};

__device__ __forceinline__ void load_chunk(const Job& jb, int c, int m0, int n0,
                                           int tid, uint4 rA[4], uint4 rW[2]) {
    const Seg& S = (c < jb.s[0].chunks) ? jb.s[0] : jb.s[1];
    const int cc = (c < jb.s[0].chunks) ? c : c - jb.s[0].chunks;
    const int col0 = cc * KC;
    const size_t kp = S.kpad;
    const int r0 = tid >> 2,          c16a = (tid & 3) * 8;
    const int r1 = (tid + 256) >> 2,  c16b = ((tid + 256) & 3) * 8;
    const __nv_bfloat16* ah = S.Ah + (size_t)m0 * kp + col0;
    const __nv_bfloat16* al = S.Al + (size_t)m0 * kp + col0;
    rA[0] = *(const uint4*)(ah + (size_t)r0 * kp + c16a);
    rA[1] = *(const uint4*)(ah + (size_t)r1 * kp + c16b);
    rA[2] = *(const uint4*)(al + (size_t)r0 * kp + c16a);
    rA[3] = *(const uint4*)(al + (size_t)r1 * kp + c16b);
    const int nr = tid >> 2, nc = (tid & 3) * 8;
    rW[0] = *(const uint4*)(S.Wh + (size_t)(n0 + nr) * kp + col0 + nc);
    rW[1] = *(const uint4*)(S.Wl + (size_t)(n0 + nr) * kp + col0 + nc);
}

__device__ __forceinline__ void store_stage(__nv_bfloat16* st, int tid,
                                            const uint4 rA[4], const uint4 rW[2]) {
    const int r0 = tid >> 2,          c16a = (tid & 3) * 8;
    const int r1 = (tid + 256) >> 2,  c16b = ((tid + 256) & 3) * 8;
    *(uint4*)(st + r0 * SST + c16a) = rA[0];
    *(uint4*)(st + r1 * SST + c16b) = rA[1];
    *(uint4*)(st + A_TILE + r0 * SST + c16a) = rA[2];
    *(uint4*)(st + A_TILE + r1 * SST + c16b) = rA[3];
    const int nr = tid >> 2, nc = (tid & 3) * 8;
    *(uint4*)(st + 2 * A_TILE + nr * SST + nc) = rW[0];
    *(uint4*)(st + 2 * A_TILE + W_TILE + nr * SST + nc) = rW[1];
}

__device__ __forceinline__ void compute_chunk(const __nv_bfloat16* st,
                                              int wm0, int wn0, int r0, int c0,
                                              float acc[2][4][4]) {
    const __nv_bfloat16* Ah = st;
    const __nv_bfloat16* Al = st + A_TILE;
    const __nv_bfloat16* Wh = st + 2 * A_TILE;
    const __nv_bfloat16* Wl = st + 2 * A_TILE + W_TILE;
    #pragma unroll
    for (int s = 0; s < 2; s++) {
        const int kk = s * 16 + c0;
        uint32_t ah[2][4], al[2][4], bh[4][2], bl[4][2];
        #pragma unroll
        for (int i = 0; i < 2; i++) {
            const __nv_bfloat16* p = Ah + (wm0 + i * 16 + r0) * SST + kk;
            ah[i][0] = *(const uint32_t*)(p);
            ah[i][1] = *(const uint32_t*)(p + 8 * SST);
            ah[i][2] = *(const uint32_t*)(p + 8);
            ah[i][3] = *(const uint32_t*)(p + 8 * SST + 8);
            const __nv_bfloat16* q = Al + (wm0 + i * 16 + r0) * SST + kk;
            al[i][0] = *(const uint32_t*)(q);
            al[i][1] = *(const uint32_t*)(q + 8 * SST);
            al[i][2] = *(const uint32_t*)(q + 8);
            al[i][3] = *(const uint32_t*)(q + 8 * SST + 8);
        }
        #pragma unroll
        for (int j = 0; j < 4; j++) {
            const __nv_bfloat16* p = Wh + (wn0 + j * 8 + r0) * SST + kk;
            bh[j][0] = *(const uint32_t*)(p);
            bh[j][1] = *(const uint32_t*)(p + 8);
            const __nv_bfloat16* q = Wl + (wn0 + j * 8 + r0) * SST + kk;
            bl[j][0] = *(const uint32_t*)(q);
            bl[j][1] = *(const uint32_t*)(q + 8);
        }
        #pragma unroll
        for (int i = 0; i < 2; i++)
            #pragma unroll
            for (int j = 0; j < 4; j++) {
                mma_bf16(acc[i][j], ah[i], bh[j]);
                mma_bf16(acc[i][j], ah[i], bl[j]);
                mma_bf16(acc[i][j], al[i], bh[j]);
            }
    }
}

__global__ __launch_bounds__(TPB, 2) void cell_kernel(Job jH, Job jL,
                                                      int cidx, int ntiles) {
    extern __shared__ __nv_bfloat16 sm[];
    __shared__ float s_bias[NTILE];
    __shared__ unsigned int s_idx;

    const int tid = threadIdx.x, lane = tid & 31, wid = tid >> 5;
    const int wm0 = (wid & 3) * 32;      // warp m offset in tile
    const int wn0 = (wid >> 2) * 32;     // warp n offset in tile
    const int r0 = lane >> 2;            // fragment row group
    const int c0 = (lane & 3) * 2;       // fragment col group

    for (;;) {
        if (tid == 0) s_idx = atomicAdd(&g_counter[cidx], 1u);
        __syncthreads();
        const unsigned int idx = s_idx;
        if (idx >= (unsigned int)ntiles) break;

        const Job& jb = (idx < TILES) ? jH : jL;
        const int tile = (idx < TILES) ? (int)idx : (int)idx - TILES;
        const int m0 = (tile / NT) * MTILE;
        const int n0 = (tile % NT) * NTILE;

        if (tid < NTILE) {
            int n = n0 + tid;
            s_bias[tid] = (n < HID) ? (jb.b1[n] + jb.b2[n]) : 0.0f;
        }

        float acc[2][4][4] = {};
        const int nch = jb.s[0].chunks + jb.s[1].chunks;

        uint4 rA[4], rW[2];
        load_chunk(jb, 0, m0, n0, tid, rA, rW);
        store_stage(sm, tid, rA, rW);
        __syncthreads();

        for (int c = 0; c < nch; c++) {
            if (c + 1 < nch) load_chunk(jb, c + 1, m0, n0, tid, rA, rW);
            compute_chunk(sm + (c & 1) * STAGE, wm0, wn0, r0, c0, acc);
            if (c + 1 < nch) store_stage(sm + ((c + 1) & 1) * STAGE, tid, rA, rW);
            __syncthreads();
        }

        // epilogue: bias + tanh, store h as bf16 hi/lo pairs
        #pragma unroll
        for (int i = 0; i < 2; i++) {
            const int grow = m0 + wm0 + i * 16 + r0;
            #pragma unroll
            for (int j = 0; j < 4; j++) {
                const int col = wn0 + j * 8 + c0;       // local col (even)
                const float bv0 = s_bias[col], bv1 = s_bias[col + 1];
                const size_t o0 = (size_t)grow * HPAD + n0 + col;
                const size_t o1 = (size_t)(grow + 8) * HPAD + n0 + col;
                float t00 = fast_tanh(acc[i][j][0] + bv0);
                float t01 = fast_tanh(acc[i][j][1] + bv1);
                float t10 = fast_tanh(acc[i][j][2] + bv0);
                float t11 = fast_tanh(acc[i][j][3] + bv1);
                uint32_t u0 = pkbf(t00, t01);
                uint32_t u1 = pkbf(t10, t11);
                *(uint32_t*)(jb.Ch + o0) = u0;
                *(uint32_t*)(jb.Ch + o1) = u1;
                float s00 = t00 - __uint_as_float(u0 << 16);
                float s01 = t01 - __uint_as_float(u0 & 0xFFFF0000u);
                float s10 = t10 - __uint_as_float(u1 << 16);
                float s11 = t11 - __uint_as_float(u1 & 0xFFFF0000u);
                *(uint32_t*)(jb.Cl + o0) = pkbf(s00, s01);
                *(uint32_t*)(jb.Cl + o1) = pkbf(s10, s11);
            }
        }
        // loop-top __syncthreads guards smem/s_bias reuse
    }
}

// ---------------- classifier ----------------
__global__ void classifier_kernel(const __nv_bfloat16* __restrict__ hh,
                                  const __nv_bfloat16* __restrict__ hl,
                                  const float* __restrict__ Wout,
                                  const float* __restrict__ bout,
                                  float* __restrict__ out) {
    int warp = (blockIdx.x * blockDim.x + threadIdx.x) >> 5;
    int lane = threadIdx.x & 31;
    if (warp >= BATCH * OUTDIM) return;
    int b = warp / OUTDIM, o = warp % OUTDIM;
    const __nv_bfloat16* rh = hh + (size_t)b * HPAD;
    const __nv_bfloat16* rl = hl + (size_t)b * HPAD;
    const float* wr = Wout + (size_t)o * HID;
    float s = 0.0f;
    for (int k = lane; k < HID; k += 32)
        s += (__bfloat162float(rh[k]) + __bfloat162float(rl[k])) * wr[k];
    #pragma unroll
    for (int off = 16; off; off >>= 1) s += __shfl_down_sync(0xffffffff, s, off);
    if (lane == 0) out[b * OUTDIM + o] = s + bout[o];
}

// ---------------- host ----------------
extern "C" void kernel_launch(void* const* d_in, const int* in_sizes, int n_in,
                              void* d_out, int out_size) {
    const float* xs   = (const float*)d_in[0];
    const float* Wih0 = (const float*)d_in[1];
    const float* Whh0 = (const float*)d_in[2];
    const float* bih0 = (const float*)d_in[3];
    const float* bhh0 = (const float*)d_in[4];
    const float* Wih1 = (const float*)d_in[5];
    const float* Whh1 = (const float*)d_in[6];
    const float* bih1 = (const float*)d_in[7];
    const float* bhh1 = (const float*)d_in[8];
    const float* Wout = (const float*)d_in[9];
    const float* bout = (const float*)d_in[10];
    float* out = (float*)d_out;

    static int attr_done = 0;
    if (!attr_done) {
        cudaFuncSetAttribute(cell_kernel, cudaFuncAttributeMaxDynamicSharedMemorySize,
                             SMEM_BYTES);
        attr_done = 1;
    }

    void* p;
    __nv_bfloat16 *xh, *xl, *wh, *wl, *h0h, *h0l, *h1h, *h1l;
    cudaGetSymbolAddress(&p, gx_h);  xh  = (__nv_bfloat16*)p;
    cudaGetSymbolAddress(&p, gx_l);  xl  = (__nv_bfloat16*)p;
    cudaGetSymbolAddress(&p, gW_h);  wh  = (__nv_bfloat16*)p;
    cudaGetSymbolAddress(&p, gW_l);  wl  = (__nv_bfloat16*)p;
    cudaGetSymbolAddress(&p, gh0_h); h0h = (__nv_bfloat16*)p;
    cudaGetSymbolAddress(&p, gh0_l); h0l = (__nv_bfloat16*)p;
    cudaGetSymbolAddress(&p, gh1_h); h1h = (__nv_bfloat16*)p;
    cudaGetSymbolAddress(&p, gh1_l); h1l = (__nv_bfloat16*)p;

    // split/pad weights & x to bf16 hi/lo; zero h state + counters
    {
        long tx = (long)TSTEPS * BATCH * XPAD;
        convert_pad_kernel<<<(unsigned)((tx + 255) / 256), 256>>>(
            xh, xl, xs, TSTEPS * BATCH, INDIM, XPAD, tx);
        long t0 = (long)NPAD * XPAD;
        convert_pad_kernel<<<(unsigned)((t0 + 255) / 256), 256>>>(
            wh + W_IH0_OFF, wl + W_IH0_OFF, Wih0, HID, INDIM, XPAD, t0);
        long th = (long)NPAD * HPAD;
        convert_pad_kernel<<<(unsigned)((th + 255) / 256), 256>>>(
            wh + W_HH0_OFF, wl + W_HH0_OFF, Whh0, HID, HID, HPAD, th);
        convert_pad_kernel<<<(unsigned)((th + 255) / 256), 256>>>(
            wh + W_IH1_OFF, wl + W_IH1_OFF, Wih1, HID, HID, HPAD, th);
        convert_pad_kernel<<<(unsigned)((th + 255) / 256), 256>>>(
            wh + W_HH1_OFF, wl + W_HH1_OFF, Whh1, HID, HID, HPAD, th);
        init_kernel<<<(2 * BATCH * HPAD + 255) / 256, 256>>>();
    }

    const size_t HP = (size_t)BATCH * HPAD;
    const size_t XT = (size_t)BATCH * XPAD;

    // t = 0: layer0 only
    {
        Job j0;
        j0.s[0] = { xh, xl, wh + W_IH0_OFF, wl + W_IH0_OFF, XPAD, XPAD / KC };
        j0.s[1] = { h0h + HP, h0l + HP, wh + W_HH0_OFF, wl + W_HH0_OFF, HPAD, HPAD / KC };
        j0.b1 = bih0; j0.b2 = bhh0;
        j0.Ch = h0h; j0.Cl = h0l;                       // parity 0
        cell_kernel<<<GRID, TPB, SMEM_BYTES>>>(j0, j0, 0, TILES);
    }

    // t = 1..127: fused  h0(t) || h1(t-1); heavy layer1 job first
    for (int t = 1; t < TSTEPS; t++) {
        const size_t pPrev = (size_t)((t - 1) & 1) * HP;
        const size_t pCur  = (size_t)(t & 1) * HP;
        Job j1;   // h1(t-1) = g(h0(t-1), h1(t-2))
        j1.s[0] = { h0h + pPrev, h0l + pPrev, wh + W_IH1_OFF, wl + W_IH1_OFF, HPAD, HPAD / KC };
        j1.s[1] = { h1h + pCur,  h1l + pCur,  wh + W_HH1_OFF, wl + W_HH1_OFF, HPAD, HPAD / KC };
        j1.b1 = bih1; j1.b2 = bhh1;
        j1.Ch = h1h + pPrev; j1.Cl = h1l + pPrev;
        Job j0;   // h0(t) = f(x_t, h0(t-1))
        j0.s[0] = { xh + (size_t)t * XT, xl + (size_t)t * XT,
                    wh + W_IH0_OFF, wl + W_IH0_OFF, XPAD, XPAD / KC };
        j0.s[1] = { h0h + pPrev, h0l + pPrev, wh + W_HH0_OFF, wl + W_HH0_OFF, HPAD, HPAD / KC };
        j0.b1 = bih0; j0.b2 = bhh0;
        j0.Ch = h0h + pCur; j0.Cl = h0l + pCur;
        cell_kernel<<<GRID, TPB, SMEM_BYTES>>>(j1, j0, t, 2 * TILES);
    }

    // drain: h1(127) = g(h0(127) [parity 1], h1(126) [parity 0]) -> parity 1
    {
        Job jf;
        jf.s[0] = { h0h + HP, h0l + HP, wh + W_IH1_OFF, wl + W_IH1_OFF, HPAD, HPAD / KC };
        jf.s[1] = { h1h, h1l, wh + W_HH1_OFF, wl + W_HH1_OFF, HPAD, HPAD / KC };
        jf.b1 = bih1; jf.b2 = bhh1;
        jf.Ch = h1h + HP; jf.Cl = h1l + HP;
        cell_kernel<<<GRID, TPB, SMEM_BYTES>>>(jf, jf, TSTEPS, TILES);
    }

    classifier_kernel<<<(BATCH * OUTDIM * 32 + 255) / 256, 256>>>(
        h1h + HP, h1l + HP, Wout, bout, out);
}

// round 8
// speedup vs baseline: 4.2063x; 1.1813x over previous
#include <cuda_runtime.h>
#include <cuda_bf16.h>
#include <stdint.h>
#include <math.h>

// ---------------- problem constants ----------------
#define TSTEPS 128
#define BATCH  1024
#define INDIM  47
#define HID    646
#define OUTDIM 5

// ---------------- tiling ----------------
#define MTILE 128
#define NTILE 64
#define KC    32                  // k-chunk (bf16)
#define NT    11                  // 704/64
#define TILES 88                  // per job
#define NPAD  704
#define HPAD  704
#define XPAD  64
#define TPB   256
#define GRID  296

#define SST    40                 // smem row stride (bf16)
#define A_TILE (MTILE * SST)      // 5120 bf16
#define W_TILE (NTILE * SST)      // 2560 bf16
#define STAGE  (2 * A_TILE + 2 * W_TILE)   // 15360 bf16
#define SMEM_BYTES (2 * STAGE * 2)         // 61440 B

// ---------------- device globals (no allocation allowed) ----------------
#define W_IH0_OFF 0
#define W_HH0_OFF (NPAD * XPAD)
#define W_IH1_OFF (W_HH0_OFF + NPAD * HPAD)
#define W_HH1_OFF (W_IH1_OFF + NPAD * HPAD)
#define W_TOT     (W_HH1_OFF + NPAD * HPAD)

__device__ __align__(16) __nv_bfloat16 gx_h[(size_t)TSTEPS * BATCH * XPAD];
__device__ __align__(16) __nv_bfloat16 gx_l[(size_t)TSTEPS * BATCH * XPAD];
__device__ __align__(16) __nv_bfloat16 gW_h[W_TOT];
__device__ __align__(16) __nv_bfloat16 gW_l[W_TOT];
__device__ __align__(16) __nv_bfloat16 gh0_h[2 * BATCH * HPAD];
__device__ __align__(16) __nv_bfloat16 gh0_l[2 * BATCH * HPAD];
__device__ __align__(16) __nv_bfloat16 gh1_h[2 * BATCH * HPAD];
__device__ __align__(16) __nv_bfloat16 gh1_l[2 * BATCH * HPAD];
__device__ unsigned int g_counter[TSTEPS + 2];

// ---------------- helpers ----------------
__device__ __forceinline__ uint32_t pkbf(float lo, float hi) {
    uint32_t r;
    asm("cvt.rn.bf16x2.f32 %0, %1, %2;" : "=r"(r) : "f"(hi), "f"(lo));
    return r;
}
__device__ __forceinline__ float fast_tanh(float x) {
    float e = __expf(2.0f * x);
    return 1.0f - __fdividef(2.0f, e + 1.0f);
}
__device__ __forceinline__ void mma_bf16(float* d, const uint32_t a[4], const uint32_t* b) {
    asm volatile(
        "mma.sync.aligned.m16n8k16.row.col.f32.bf16.bf16.f32 "
        "{%0,%1,%2,%3}, {%4,%5,%6,%7}, {%8,%9}, {%0,%1,%2,%3};"
        : "+f"(d[0]), "+f"(d[1]), "+f"(d[2]), "+f"(d[3])
        : "r"(a[0]), "r"(a[1]), "r"(a[2]), "r"(a[3]), "r"(b[0]), "r"(b[1]));
}
#define LDSM_X4(R, addr) \
    asm volatile("ldmatrix.sync.aligned.m8n8.x4.shared.b16 {%0,%1,%2,%3}, [%4];" \
        : "=r"((R)[0]), "=r"((R)[1]), "=r"((R)[2]), "=r"((R)[3]) : "r"(addr))
#define CPA16(dst, src) \
    asm volatile("cp.async.cg.shared.global [%0], [%1], 16;" :: "r"(dst), "l"(src))
#define CPA_COMMIT() asm volatile("cp.async.commit_group;" ::: "memory")
#define CPA_WAIT0()  asm volatile("cp.async.wait_group 0;" ::: "memory")
#define CPA_WAIT1()  asm volatile("cp.async.wait_group 1;" ::: "memory")

// ---------------- preprocessing ----------------
__global__ void convert_pad_kernel(__nv_bfloat16* dh, __nv_bfloat16* dl,
                                   const float* __restrict__ src,
                                   int rreal, int creal, int cpad, long total) {
    long i = (long)blockIdx.x * blockDim.x + threadIdx.x;
    if (i >= total) return;
    int r = (int)(i / cpad), c = (int)(i % cpad);
    float v = (r < rreal && c < creal) ? src[(long)r * creal + c] : 0.0f;
    __nv_bfloat16 hi = __float2bfloat16(v);
    dh[i] = hi;
    dl[i] = __float2bfloat16(v - __bfloat162float(hi));
}

__global__ void init_kernel() {
    int i = blockIdx.x * blockDim.x + threadIdx.x;
    __nv_bfloat16 z = __float2bfloat16(0.0f);
    if (i < 2 * BATCH * HPAD) {
        gh0_h[i] = z; gh0_l[i] = z; gh1_h[i] = z; gh1_l[i] = z;
    }
    if (i < TSTEPS + 2) g_counter[i] = 0u;
}

// ---------------- cell kernel ----------------
struct Seg {
    const __nv_bfloat16 *Ah, *Al;
    const __nv_bfloat16 *Wh, *Wl;
    int kpad, chunks;
};
struct Job {
    Seg s[2];
    const float *b1, *b2;
    __nv_bfloat16 *Ch, *Cl;
};

// issue cp.async for chunk c into stage buffer (6 x 16B per thread)
__device__ __forceinline__ void issue_chunk(const Job& jb, int c, int m0, int n0,
                                            int tid, uint32_t st_u32) {
    const Seg& S = (c < jb.s[0].chunks) ? jb.s[0] : jb.s[1];
    const int cc = (c < jb.s[0].chunks) ? c : c - jb.s[0].chunks;
    const int col0 = cc * KC;
    const size_t kp = S.kpad;
    // A: 512 x 16B per half; thread covers ids {tid, tid+256}
    const int r0 = tid >> 2,          c8a = (tid & 3) * 8;
    const int r1 = (tid + 256) >> 2,  c8b = ((tid + 256) & 3) * 8;
    const __nv_bfloat16* ah = S.Ah + (size_t)m0 * kp + col0;
    const __nv_bfloat16* al = S.Al + (size_t)m0 * kp + col0;
    CPA16(st_u32 + (r0 * SST + c8a) * 2,                ah + (size_t)r0 * kp + c8a);
    CPA16(st_u32 + (r1 * SST + c8b) * 2,                ah + (size_t)r1 * kp + c8b);
    CPA16(st_u32 + (A_TILE + r0 * SST + c8a) * 2,       al + (size_t)r0 * kp + c8a);
    CPA16(st_u32 + (A_TILE + r1 * SST + c8b) * 2,       al + (size_t)r1 * kp + c8b);
    // W: 256 x 16B per half; one id per thread
    const int nr = tid >> 2, nc = (tid & 3) * 8;
    CPA16(st_u32 + (2 * A_TILE + nr * SST + nc) * 2,
          S.Wh + (size_t)(n0 + nr) * kp + col0 + nc);
    CPA16(st_u32 + (2 * A_TILE + W_TILE + nr * SST + nc) * 2,
          S.Wl + (size_t)(n0 + nr) * kp + col0 + nc);
}

__global__ __launch_bounds__(TPB, 2) void cell_kernel(Job jH, Job jL,
                                                      int cidx, int ntiles) {
    extern __shared__ __nv_bfloat16 sm[];
    __shared__ float s_bias[NTILE];
    __shared__ unsigned int s_idx;

    const int tid = threadIdx.x, lane = tid & 31, wid = tid >> 5;
    const int wm0 = (wid & 3) * 32;      // warp m offset
    const int wn0 = (wid >> 2) * 32;     // warp n offset
    const int r0 = lane >> 2;            // fragment row group
    const int c0 = (lane & 3) * 2;       // fragment col group

    const uint32_t sm_u32 = (uint32_t)__cvta_generic_to_shared(sm);

    // ldmatrix lane addressing: t = tile index within x4, r = row within tile
    const int lt = lane >> 3, lr = lane & 7;
    // A x4 tiles (m16k16): t0=(r0-7,k0) t1=(r8-15,k0) t2=(r0-7,k8) t3=(r8-15,k8)
    // offset (bf16 elems) for tile block (i, s):
    uint32_t offA[2][2];
    #pragma unroll
    for (int i = 0; i < 2; i++)
        #pragma unroll
        for (int s = 0; s < 2; s++)
            offA[i][s] = ((wm0 + i * 16 + (lt & 1) * 8 + lr) * SST + s * 16 + (lt >> 1) * 8) * 2;
    // B x4 tiles (two n8k16 j-blocks): t0=(j,k0) t1=(j,k8) t2=(j+1,k0) t3=(j+1,k8)
    uint32_t offB[2][2];
    #pragma unroll
    for (int jp = 0; jp < 2; jp++)
        #pragma unroll
        for (int s = 0; s < 2; s++)
            offB[jp][s] = ((wn0 + (2 * jp + (lt >> 1)) * 8 + lr) * SST + s * 16 + (lt & 1) * 8) * 2;

    for (;;) {
        if (tid == 0) s_idx = atomicAdd(&g_counter[cidx], 1u);
        __syncthreads();
        const unsigned int idx = s_idx;
        if (idx >= (unsigned int)ntiles) break;

        const Job& jb = (idx < TILES) ? jH : jL;
        const int tile = (idx < TILES) ? (int)idx : (int)idx - TILES;
        const int m0 = (tile / NT) * MTILE;
        const int n0 = (tile % NT) * NTILE;

        if (tid < NTILE) {
            int n = n0 + tid;
            s_bias[tid] = (n < HID) ? (jb.b1[n] + jb.b2[n]) : 0.0f;
        }

        float acc[2][4][4] = {};
        const int nch = jb.s[0].chunks + jb.s[1].chunks;

        issue_chunk(jb, 0, m0, n0, tid, sm_u32);
        CPA_COMMIT();

        for (int c = 0; c < nch; c++) {
            if (c + 1 < nch) {
                issue_chunk(jb, c + 1, m0, n0, tid, sm_u32 + ((c + 1) & 1) * STAGE * 2);
                CPA_COMMIT();
                CPA_WAIT1();
            } else {
                CPA_WAIT0();
            }
            __syncthreads();

            const uint32_t sb = sm_u32 + (c & 1) * STAGE * 2;
            #pragma unroll
            for (int s = 0; s < 2; s++) {
                uint32_t ah[2][4], al[2][4], bh[2][4], bl[2][4];
                #pragma unroll
                for (int i = 0; i < 2; i++) {
                    LDSM_X4(ah[i], sb + offA[i][s]);
                    LDSM_X4(al[i], sb + offA[i][s] + A_TILE * 2);
                }
                #pragma unroll
                for (int jp = 0; jp < 2; jp++) {
                    LDSM_X4(bh[jp], sb + offB[jp][s] + 2 * A_TILE * 2);
                    LDSM_X4(bl[jp], sb + offB[jp][s] + (2 * A_TILE + W_TILE) * 2);
                }
                #pragma unroll
                for (int i = 0; i < 2; i++)
                    #pragma unroll
                    for (int j = 0; j < 4; j++) {
                        const uint32_t* pbh = &bh[j >> 1][(j & 1) * 2];
                        const uint32_t* pbl = &bl[j >> 1][(j & 1) * 2];
                        mma_bf16(acc[i][j], ah[i], pbh);
                        mma_bf16(acc[i][j], ah[i], pbl);
                        mma_bf16(acc[i][j], al[i], pbh);
                    }
            }
            __syncthreads();
        }

        // epilogue: bias + tanh, store h as bf16 hi/lo pairs
        #pragma unroll
        for (int i = 0; i < 2; i++) {
            const int grow = m0 + wm0 + i * 16 + r0;
            #pragma unroll
            for (int j = 0; j < 4; j++) {
                const int col = wn0 + j * 8 + c0;
                const float bv0 = s_bias[col], bv1 = s_bias[col + 1];
                const size_t o0 = (size_t)grow * HPAD + n0 + col;
                const size_t o1 = (size_t)(grow + 8) * HPAD + n0 + col;
                float t00 = fast_tanh(acc[i][j][0] + bv0);
                float t01 = fast_tanh(acc[i][j][1] + bv1);
                float t10 = fast_tanh(acc[i][j][2] + bv0);
                float t11 = fast_tanh(acc[i][j][3] + bv1);
                uint32_t u0 = pkbf(t00, t01);
                uint32_t u1 = pkbf(t10, t11);
                *(uint32_t*)(jb.Ch + o0) = u0;
                *(uint32_t*)(jb.Ch + o1) = u1;
                float s00 = t00 - __uint_as_float(u0 << 16);
                float s01 = t01 - __uint_as_float(u0 & 0xFFFF0000u);
                float s10 = t10 - __uint_as_float(u1 << 16);
                float s11 = t11 - __uint_as_float(u1 & 0xFFFF0000u);
                *(uint32_t*)(jb.Cl + o0) = pkbf(s00, s01);
                *(uint32_t*)(jb.Cl + o1) = pkbf(s10, s11);
            }
        }
    }
}

// ---------------- classifier ----------------
__global__ void classifier_kernel(const __nv_bfloat16* __restrict__ hh,
                                  const __nv_bfloat16* __restrict__ hl,
                                  const float* __restrict__ Wout,
                                  const float* __restrict__ bout,
                                  float* __restrict__ out) {
    int warp = (blockIdx.x * blockDim.x + threadIdx.x) >> 5;
    int lane = threadIdx.x & 31;
    if (warp >= BATCH * OUTDIM) return;
    int b = warp / OUTDIM, o = warp % OUTDIM;
    const __nv_bfloat16* rh = hh + (size_t)b * HPAD;
    const __nv_bfloat16* rl = hl + (size_t)b * HPAD;
    const float* wr = Wout + (size_t)o * HID;
    float s = 0.0f;
    for (int k = lane; k < HID; k += 32)
        s += (__bfloat162float(rh[k]) + __bfloat162float(rl[k])) * wr[k];
    #pragma unroll
    for (int off = 16; off; off >>= 1) s += __shfl_down_sync(0xffffffff, s, off);
    if (lane == 0) out[b * OUTDIM + o] = s + bout[o];
}

// ---------------- host ----------------
extern "C" void kernel_launch(void* const* d_in, const int* in_sizes, int n_in,
                              void* d_out, int out_size) {
    const float* xs   = (const float*)d_in[0];
    const float* Wih0 = (const float*)d_in[1];
    const float* Whh0 = (const float*)d_in[2];
    const float* bih0 = (const float*)d_in[3];
    const float* bhh0 = (const float*)d_in[4];
    const float* Wih1 = (const float*)d_in[5];
    const float* Whh1 = (const float*)d_in[6];
    const float* bih1 = (const float*)d_in[7];
    const float* bhh1 = (const float*)d_in[8];
    const float* Wout = (const float*)d_in[9];
    const float* bout = (const float*)d_in[10];
    float* out = (float*)d_out;

    static int attr_done = 0;
    if (!attr_done) {
        cudaFuncSetAttribute(cell_kernel, cudaFuncAttributeMaxDynamicSharedMemorySize,
                             SMEM_BYTES);
        attr_done = 1;
    }

    void* p;
    __nv_bfloat16 *xh, *xl, *wh, *wl, *h0h, *h0l, *h1h, *h1l;
    cudaGetSymbolAddress(&p, gx_h);  xh  = (__nv_bfloat16*)p;
    cudaGetSymbolAddress(&p, gx_l);  xl  = (__nv_bfloat16*)p;
    cudaGetSymbolAddress(&p, gW_h);  wh  = (__nv_bfloat16*)p;
    cudaGetSymbolAddress(&p, gW_l);  wl  = (__nv_bfloat16*)p;
    cudaGetSymbolAddress(&p, gh0_h); h0h = (__nv_bfloat16*)p;
    cudaGetSymbolAddress(&p, gh0_l); h0l = (__nv_bfloat16*)p;
    cudaGetSymbolAddress(&p, gh1_h); h1h = (__nv_bfloat16*)p;
    cudaGetSymbolAddress(&p, gh1_l); h1l = (__nv_bfloat16*)p;

    {
        long tx = (long)TSTEPS * BATCH * XPAD;
        convert_pad_kernel<<<(unsigned)((tx + 255) / 256), 256>>>(
            xh, xl, xs, TSTEPS * BATCH, INDIM, XPAD, tx);
        long t0 = (long)NPAD * XPAD;
        convert_pad_kernel<<<(unsigned)((t0 + 255) / 256), 256>>>(
            wh + W_IH0_OFF, wl + W_IH0_OFF, Wih0, HID, INDIM, XPAD, t0);
        long th = (long)NPAD * HPAD;
        convert_pad_kernel<<<(unsigned)((th + 255) / 256), 256>>>(
            wh + W_HH0_OFF, wl + W_HH0_OFF, Whh0, HID, HID, HPAD, th);
        convert_pad_kernel<<<(unsigned)((th + 255) / 256), 256>>>(
            wh + W_IH1_OFF, wl + W_IH1_OFF, Wih1, HID, HID, HPAD, th);
        convert_pad_kernel<<<(unsigned)((th + 255) / 256), 256>>>(
            wh + W_HH1_OFF, wl + W_HH1_OFF, Whh1, HID, HID, HPAD, th);
        init_kernel<<<(2 * BATCH * HPAD + 255) / 256, 256>>>();
    }

    const size_t HP = (size_t)BATCH * HPAD;
    const size_t XT = (size_t)BATCH * XPAD;

    // t = 0: layer0 only
    {
        Job j0;
        j0.s[0] = { xh, xl, wh + W_IH0_OFF, wl + W_IH0_OFF, XPAD, XPAD / KC };
        j0.s[1] = { h0h + HP, h0l + HP, wh + W_HH0_OFF, wl + W_HH0_OFF, HPAD, HPAD / KC };
        j0.b1 = bih0; j0.b2 = bhh0;
        j0.Ch = h0h; j0.Cl = h0l;
        cell_kernel<<<GRID, TPB, SMEM_BYTES>>>(j0, j0, 0, TILES);
    }

    // t = 1..127: fused h0(t) || h1(t-1); heavy layer1 job first
    for (int t = 1; t < TSTEPS; t++) {
        const size_t pPrev = (size_t)((t - 1) & 1) * HP;
        const size_t pCur  = (size_t)(t & 1) * HP;
        Job j1;
        j1.s[0] = { h0h + pPrev, h0l + pPrev, wh + W_IH1_OFF, wl + W_IH1_OFF, HPAD, HPAD / KC };
        j1.s[1] = { h1h + pCur,  h1l + pCur,  wh + W_HH1_OFF, wl + W_HH1_OFF, HPAD, HPAD / KC };
        j1.b1 = bih1; j1.b2 = bhh1;
        j1.Ch = h1h + pPrev; j1.Cl = h1l + pPrev;
        Job j0;
        j0.s[0] = { xh + (size_t)t * XT, xl + (size_t)t * XT,
                    wh + W_IH0_OFF, wl + W_IH0_OFF, XPAD, XPAD / KC };
        j0.s[1] = { h0h + pPrev, h0l + pPrev, wh + W_HH0_OFF, wl + W_HH0_OFF, HPAD, HPAD / KC };
        j0.b1 = bih0; j0.b2 = bhh0;
        j0.Ch = h0h + pCur; j0.Cl = h0l + pCur;
        cell_kernel<<<GRID, TPB, SMEM_BYTES>>>(j1, j0, t, 2 * TILES);
    }

    // drain: h1(127)
    {
        Job jf;
        jf.s[0] = { h0h + HP, h0l + HP, wh + W_IH1_OFF, wl + W_IH1_OFF, HPAD, HPAD / KC };
        jf.s[1] = { h1h, h1l, wh + W_HH1_OFF, wl + W_HH1_OFF, HPAD, HPAD / KC };
        jf.b1 = bih1; jf.b2 = bhh1;
        jf.Ch = h1h + HP; jf.Cl = h1l + HP;
        cell_kernel<<<GRID, TPB, SMEM_BYTES>>>(jf, jf, TSTEPS, TILES);
    }

    classifier_kernel<<<(BATCH * OUTDIM * 32 + 255) / 256, 256>>>(
        h1h + HP, h1l + HP, Wout, bout, out);
}